// round 9
// baseline (speedup 1.0000x reference)
#include <cuda_runtime.h>

// tanhP1 bitstream stencil — R3 structure + 16-row phase-separated groups.
// out[t] = n5 * x[t-8]:
//   n1 = x[t]*x[t-4]
//   n2 = 1 - n1*c2[t]
//   n3 = 1 - n2*c3[t]*n1[t-1]
//   n4 = 1 - n3*c4[t]*n1[t-2]
//   n5 = 1 - n4*c5[t]*n1[t-3]
// Exact {0,1} floats -> FFMA arithmetic is bit-exact.
//
// Round-8 rationale (vs R3, the 6.11 TB/s best):
//  * 16-row groups with strict phase separation: 16 back-to-back loads
//    (MLP=16), 16 computes IN-PLACE (outputs overwrite the load registers,
//    so no extra array), then 16 back-to-back stores. Longer homogeneous
//    read/write bursts per warp -> fewer DRAM bus turnarounds; 2x per-warp
//    bytes in flight. Zero traffic change.
//  * everything else identical to R3: float2 columns, CH=64 chunks,
//    col-fastest grid, shared c-table, no streaming hints.

#define TT 256
#define CH 64          // chunk length (multiple of 16)
#define GR 16          // rows per load/compute/store group

__global__ __launch_bounds__(256)
void tanhP1_kernel(const float2* __restrict__ x,
                   const float*  __restrict__ c2,
                   const float*  __restrict__ c3,
                   const float*  __restrict__ c4,
                   const float*  __restrict__ c5,
                   float2* __restrict__ out,
                   int n2)   // N/2 float2 columns
{
    __shared__ float4 cc[TT];
    for (int i = threadIdx.x; i < TT; i += blockDim.x)
        cc[i] = make_float4(c2[i], c3[i], c4[i], c5[i]);
    __syncthreads();

    const int col = blockIdx.x * blockDim.x + threadIdx.x;
    if (col >= n2) return;
    const int t0 = blockIdx.y * CH;          // multiple of 16

    const float2* xp = x + col;
    float2*       op = out + col;

    // Delay lines: x at time s lives in slot s&7; n1 at time s in slot s&3.
    float xh[8][2];
    float nh[4][2];

    if (t0 == 0) {
#pragma unroll
        for (int i = 0; i < 8; i++) { xh[i][0] = 0.0f; xh[i][1] = 0.0f; }
#pragma unroll
        for (int i = 0; i < 4; i++) { nh[i][0] = 0.0f; nh[i][1] = 0.0f; }
    } else {
        // Halo rows t0-8..t0-1 land in slots 0..7 (t0 % 8 == 0).
        float2 hv[8];
#pragma unroll
        for (int k = 0; k < 8; k++)
            hv[k] = xp[(long)(t0 - 8 + k) * n2];
#pragma unroll
        for (int k = 0; k < 8; k++) { xh[k][0] = hv[k].x; xh[k][1] = hv[k].y; }
        // n1[s] = x[s]*x[s-4] for s = t0-3..t0-1 -> slots 1,2,3.
#pragma unroll
        for (int l = 0; l < 2; l++) {
            nh[0][l] = 0.0f;                    // overwritten before first read
            nh[1][l] = xh[5][l] * xh[1][l];
            nh[2][l] = xh[6][l] * xh[2][l];
            nh[3][l] = xh[7][l] * xh[3][l];
        }
    }

    for (int tb = 0; tb < CH; tb += GR) {
        // ---- phase 1: 16 back-to-back independent loads (MLP = 16) ----
        float2 xv[GR];
#pragma unroll
        for (int k = 0; k < GR; k++)
            xv[k] = xp[(long)(t0 + tb + k) * n2];

        // ---- phase 2: 16 computes, outputs overwrite xv in place ----
#pragma unroll
        for (int k = 0; k < GR; k++) {
            const int t = t0 + tb + k;       // t % 8 == k & 7
            const float4 cv = cc[t];

            const int i8 = k & 7;            // x[t-8] slot (then receives x[t])
            const int i4 = (k + 4) & 7;      // x[t-4]
            const int j0 = k & 3;            // n1[t] destination
            const int j1 = (k + 3) & 3;      // n1[t-1]
            const int j2 = (k + 2) & 3;      // n1[t-2]
            const int j3 = (k + 1) & 3;      // n1[t-3]

            const float xt[2] = {xv[k].x, xv[k].y};
            float ov[2];
#pragma unroll
            for (int l = 0; l < 2; l++) {
                const float n1  = xt[l] * xh[i4][l];
                const float n2v = 1.0f - n1  * cv.x;
                const float n3  = 1.0f - n2v * (cv.y * nh[j1][l]);
                const float n4v = 1.0f - n3  * (cv.z * nh[j2][l]);
                const float n5  = 1.0f - n4v * (cv.w * nh[j3][l]);
                ov[l] = n5 * xh[i8][l];
                xh[i8][l] = xt[l];
                nh[j0][l] = n1;
            }
            xv[k] = make_float2(ov[0], ov[1]);   // in-place: xv now holds out
        }

        // ---- phase 3: 16 back-to-back stores ----
#pragma unroll
        for (int k = 0; k < GR; k++)
            op[(long)(t0 + tb + k) * n2] = xv[k];
    }
}

extern "C" void kernel_launch(void* const* d_in, const int* in_sizes, int n_in,
                              void* d_out, int out_size)
{
    const float* x  = (const float*)d_in[0];
    const float* c2 = (const float*)d_in[1];
    const float* c3 = (const float*)d_in[2];
    const float* c4 = (const float*)d_in[3];
    const float* c5 = (const float*)d_in[4];

    const int T  = in_sizes[1];           // 256
    const int N  = in_sizes[0] / T;       // 262144
    const int n2 = N / 2;                 // float2 columns

    const int threads = 256;
    dim3 grid((n2 + threads - 1) / threads, T / CH);
    tanhP1_kernel<<<grid, threads>>>((const float2*)x, c2, c3, c4, c5,
                                     (float2*)d_out, n2);
}

// round 10
// speedup vs baseline: 1.0181x; 1.0181x over previous
#include <cuda_runtime.h>

// tanhP1 bitstream stencil — R3 structure + phase-separated stores (GR=8).
// out[t] = n5 * x[t-8]:
//   n1 = x[t]*x[t-4]
//   n2 = 1 - n1*c2[t]
//   n3 = 1 - n2*c3[t]*n1[t-1]
//   n4 = 1 - n3*c4[t]*n1[t-2]
//   n5 = 1 - n4*c5[t]*n1[t-3]
// Exact {0,1} floats -> FFMA arithmetic is bit-exact.
//
// Operating point (mapped over R3-R8): float2 columns x CH=64 chunks,
// regs <= ~60 so occupancy stays >= ~44% — below that BW drops (R8: 80 regs,
// 34% occ, 5.79 TB/s), above it nothing improves (R5/R6).
// Change vs R3: stores are batched AFTER the 8 computes (outputs overwrite
// the dead load registers in place -> zero register cost). Homogeneous
// 8-row read bursts / write bursts per warp instead of interleaved R/W.

#define TT 256
#define CH 64          // chunk length (multiple of 8)
#define GR 8           // rows per load/compute/store group

__global__ __launch_bounds__(256)
void tanhP1_kernel(const float2* __restrict__ x,
                   const float*  __restrict__ c2,
                   const float*  __restrict__ c3,
                   const float*  __restrict__ c4,
                   const float*  __restrict__ c5,
                   float2* __restrict__ out,
                   int n2)   // N/2 float2 columns
{
    __shared__ float4 cc[TT];
    for (int i = threadIdx.x; i < TT; i += blockDim.x)
        cc[i] = make_float4(c2[i], c3[i], c4[i], c5[i]);
    __syncthreads();

    const int col = blockIdx.x * blockDim.x + threadIdx.x;
    if (col >= n2) return;
    const int t0 = blockIdx.y * CH;          // multiple of 8

    const float2* xp = x + col;
    float2*       op = out + col;

    // Delay lines: x at time s lives in slot s&7; n1 at time s in slot s&3.
    float xh[8][2];
    float nh[4][2];

    if (t0 == 0) {
#pragma unroll
        for (int i = 0; i < 8; i++) { xh[i][0] = 0.0f; xh[i][1] = 0.0f; }
#pragma unroll
        for (int i = 0; i < 4; i++) { nh[i][0] = 0.0f; nh[i][1] = 0.0f; }
    } else {
        // Halo rows t0-8..t0-1 land in slots 0..7 (t0 % 8 == 0).
        float2 hv[8];
#pragma unroll
        for (int k = 0; k < 8; k++)
            hv[k] = xp[(long)(t0 - 8 + k) * n2];
#pragma unroll
        for (int k = 0; k < 8; k++) { xh[k][0] = hv[k].x; xh[k][1] = hv[k].y; }
        // n1[s] = x[s]*x[s-4] for s = t0-3..t0-1 -> slots 1,2,3.
#pragma unroll
        for (int l = 0; l < 2; l++) {
            nh[0][l] = 0.0f;                    // overwritten before first read
            nh[1][l] = xh[5][l] * xh[1][l];
            nh[2][l] = xh[6][l] * xh[2][l];
            nh[3][l] = xh[7][l] * xh[3][l];
        }
    }

    for (int tb = 0; tb < CH; tb += GR) {
        // ---- phase 1: 8 back-to-back independent loads (MLP = 8) ----
        float2 xv[GR];
#pragma unroll
        for (int k = 0; k < GR; k++)
            xv[k] = xp[(long)(t0 + tb + k) * n2];

        // ---- phase 2: 8 computes, outputs overwrite xv in place ----
#pragma unroll
        for (int k = 0; k < GR; k++) {
            const int t = t0 + tb + k;       // t % 8 == k
            const float4 cv = cc[t];

            const int i8 = k;                // x[t-8] slot (then receives x[t])
            const int i4 = (k + 4) & 7;      // x[t-4]
            const int j0 = k & 3;            // n1[t] destination
            const int j1 = (k + 3) & 3;      // n1[t-1]
            const int j2 = (k + 2) & 3;      // n1[t-2]
            const int j3 = (k + 1) & 3;      // n1[t-3]

            const float xt[2] = {xv[k].x, xv[k].y};
            float ov[2];
#pragma unroll
            for (int l = 0; l < 2; l++) {
                const float n1  = xt[l] * xh[i4][l];
                const float n2v = 1.0f - n1  * cv.x;
                const float n3  = 1.0f - n2v * (cv.y * nh[j1][l]);
                const float n4v = 1.0f - n3  * (cv.z * nh[j2][l]);
                const float n5  = 1.0f - n4v * (cv.w * nh[j3][l]);
                ov[l] = n5 * xh[i8][l];
                xh[i8][l] = xt[l];
                nh[j0][l] = n1;
            }
            xv[k] = make_float2(ov[0], ov[1]);   // in place: xv now holds out
        }

        // ---- phase 3: 8 back-to-back stores ----
#pragma unroll
        for (int k = 0; k < GR; k++)
            op[(long)(t0 + tb + k) * n2] = xv[k];
    }
}

extern "C" void kernel_launch(void* const* d_in, const int* in_sizes, int n_in,
                              void* d_out, int out_size)
{
    const float* x  = (const float*)d_in[0];
    const float* c2 = (const float*)d_in[1];
    const float* c3 = (const float*)d_in[2];
    const float* c4 = (const float*)d_in[3];
    const float* c5 = (const float*)d_in[4];

    const int T  = in_sizes[1];           // 256
    const int N  = in_sizes[0] / T;       // 262144
    const int n2 = N / 2;                 // float2 columns

    const int threads = 256;
    dim3 grid((n2 + threads - 1) / threads, T / CH);
    tanhP1_kernel<<<grid, threads>>>((const float2*)x, c2, c3, c4, c5,
                                     (float2*)d_out, n2);
}

// round 11
// speedup vs baseline: 1.0534x; 1.0348x over previous
#include <cuda_runtime.h>

// tanhP1 bitstream stencil — R3 structure with CH=32 (8 concurrent chunks).
// out[t] = n5 * x[t-8]:
//   n1 = x[t]*x[t-4]
//   n2 = 1 - n1*c2[t]
//   n3 = 1 - n2*c3[t]*n1[t-1]
//   n4 = 1 - n3*c4[t]*n1[t-2]
//   n5 = 1 - n4*c5[t]*n1[t-3]
// Exact {0,1} floats -> FFMA arithmetic is bit-exact.
//
// Experiment map (R3-R10): float2 x chunked x occ>=44% gives 6.11 TB/s;
// occupancy beyond ~54%, grid order, scalar width, streaming hints, and
// store-phase separation are all neutral/negative. The only axis with a
// positive slope is chunk count (1 chunk: 5.55 -> 4 chunks: 6.11 TB/s),
// and halo rows are L2-resident while chunks overlap (DRAM-effective bytes
// measured ~499 MB < 512 MB). This round: 8 chunks (CH=32), same inner
// loop, same registers.

#define TT 256
#define CH 32          // chunk length (multiple of 8); 8 concurrent chunks

__global__ __launch_bounds__(256)
void tanhP1_kernel(const float2* __restrict__ x,
                   const float*  __restrict__ c2,
                   const float*  __restrict__ c3,
                   const float*  __restrict__ c4,
                   const float*  __restrict__ c5,
                   float2* __restrict__ out,
                   int n2)   // N/2 float2 columns
{
    __shared__ float4 cc[TT];
    for (int i = threadIdx.x; i < TT; i += blockDim.x)
        cc[i] = make_float4(c2[i], c3[i], c4[i], c5[i]);
    __syncthreads();

    const int col = blockIdx.x * blockDim.x + threadIdx.x;
    if (col >= n2) return;
    const int t0 = blockIdx.y * CH;          // multiple of 8

    const float2* xp = x + col;
    float2*       op = out + col;

    // Delay lines: x at time s lives in slot s&7; n1 at time s in slot s&3.
    float xh[8][2];
    float nh[4][2];

    if (t0 == 0) {
#pragma unroll
        for (int i = 0; i < 8; i++) { xh[i][0] = 0.0f; xh[i][1] = 0.0f; }
#pragma unroll
        for (int i = 0; i < 4; i++) { nh[i][0] = 0.0f; nh[i][1] = 0.0f; }
    } else {
        // Halo rows t0-8..t0-1 land in slots 0..7 (t0 % 8 == 0).
        float2 hv[8];
#pragma unroll
        for (int k = 0; k < 8; k++)
            hv[k] = xp[(long)(t0 - 8 + k) * n2];
#pragma unroll
        for (int k = 0; k < 8; k++) { xh[k][0] = hv[k].x; xh[k][1] = hv[k].y; }
        // n1[s] = x[s]*x[s-4] for s = t0-3..t0-1 -> slots 1,2,3.
#pragma unroll
        for (int l = 0; l < 2; l++) {
            nh[0][l] = 0.0f;                    // overwritten before first read
            nh[1][l] = xh[5][l] * xh[1][l];
            nh[2][l] = xh[6][l] * xh[2][l];
            nh[3][l] = xh[7][l] * xh[3][l];
        }
    }

    for (int tb = 0; tb < CH; tb += 8) {
        // ---- front-batch the 8 independent row loads (MLP = 8) ----
        float2 xv[8];
#pragma unroll
        for (int k = 0; k < 8; k++)
            xv[k] = xp[(long)(t0 + tb + k) * n2];

        // ---- compute + store the 8 rows ----
#pragma unroll
        for (int k = 0; k < 8; k++) {
            const int t = t0 + tb + k;       // t % 8 == k
            const float4 cv = cc[t];

            const int i8 = k;                // x[t-8] slot (then receives x[t])
            const int i4 = (k + 4) & 7;      // x[t-4]
            const int j0 = k & 3;            // n1[t] destination
            const int j1 = (k + 3) & 3;      // n1[t-1]
            const int j2 = (k + 2) & 3;      // n1[t-2]
            const int j3 = (k + 1) & 3;      // n1[t-3]

            float xt[2] = {xv[k].x, xv[k].y};
            float ov[2];
#pragma unroll
            for (int l = 0; l < 2; l++) {
                const float n1  = xt[l] * xh[i4][l];
                const float n2v = 1.0f - n1  * cv.x;
                const float n3  = 1.0f - n2v * (cv.y * nh[j1][l]);
                const float n4v = 1.0f - n3  * (cv.z * nh[j2][l]);
                const float n5  = 1.0f - n4v * (cv.w * nh[j3][l]);
                ov[l] = n5 * xh[i8][l];
                xh[i8][l] = xt[l];
                nh[j0][l] = n1;
            }
            op[(long)t * n2] = make_float2(ov[0], ov[1]);
        }
    }
}

extern "C" void kernel_launch(void* const* d_in, const int* in_sizes, int n_in,
                              void* d_out, int out_size)
{
    const float* x  = (const float*)d_in[0];
    const float* c2 = (const float*)d_in[1];
    const float* c3 = (const float*)d_in[2];
    const float* c4 = (const float*)d_in[3];
    const float* c5 = (const float*)d_in[4];

    const int T  = in_sizes[1];           // 256
    const int N  = in_sizes[0] / T;       // 262144
    const int n2 = N / 2;                 // float2 columns

    const int threads = 256;
    dim3 grid((n2 + threads - 1) / threads, T / CH);
    tanhP1_kernel<<<grid, threads>>>((const float2*)x, c2, c3, c4, c5,
                                     (float2*)d_out, n2);
}